// round 7
// baseline (speedup 1.0000x reference)
#include <cuda_runtime.h>
#include <cstdint>

// ---------------- problem constants ----------------
#define FH_   100
#define FW_   160
#define NPOS  16000          // FH*FW
#define CIN   512
#define KTOT  4608           // 9*512
#define NANCH 144000         // NPOS*9
#define PRE_NMS_  6000
#define POST_NMS_ 300
#define IMG_H 1600.0f
#define IMG_W 2560.0f

#define OFF_SCORES 0
#define OFF_REG    144000
#define OFF_PROPS  720000

// ---------------- scratch (device globals; no allocation allowed) ----------------
__device__ float              g_y[NPOS * 512];          // 32.8 MB conv1 output
__device__ float4             g_props[NANCH];           // decoded boxes
__device__ unsigned long long g_keys[NANCH];            // (ordered_score<<32)|(~idx)
__device__ unsigned long long g_cand_keys[PRE_NMS_];
__device__ float4             g_cand_boxes[PRE_NMS_];
__device__ unsigned int       g_hist[256];
__device__ unsigned long long g_prefix;
__device__ unsigned int       g_rank;
__device__ unsigned int       g_count;

// ---------------- packed fp32x2 helpers ----------------
__device__ __forceinline__ void fma2(unsigned long long& acc, unsigned long long a,
                                     unsigned long long b) {
    asm("fma.rn.f32x2 %0, %1, %2, %0;" : "+l"(acc) : "l"(a), "l"(b));
}
__device__ __forceinline__ unsigned long long bcast2(float x) {
    unsigned long long r;
    asm("mov.b64 %0, {%1, %1};" : "=l"(r) : "f"(x));
    return r;
}
__device__ __forceinline__ void unpack2(unsigned long long p, float& lo, float& hi) {
    asm("mov.b64 {%0, %1}, %2;" : "=f"(lo), "=f"(hi) : "l"(p));
}

// ---------------- reset ----------------
__global__ void k_reset() {
    int t = threadIdx.x;
    if (t < 256) g_hist[t] = 0u;
    if (t == 0) { g_prefix = 0ull; g_rank = PRE_NMS_; g_count = 0u; }
}

// ---------------- 3x3 conv, implicit GEMM: [16000 x 4608] * [4608 x 512] ----------------
// Identical arithmetic + memory schedule to the R1 passing kernel (per-element
// k-ascending FFMA chains), but inner product issued as packed fma.rn.f32x2.
__global__ __launch_bounds__(256, 2)
void k_conv3(const float* __restrict__ fm, const float* __restrict__ W1,
             const float* __restrict__ b1) {
    __shared__ float As[2][8][128];
    __shared__ float Bs[2][8][128];

    const int t  = threadIdx.x;
    const int m0 = blockIdx.x * 128;
    const int n0 = blockIdx.y * 128;

    // A-load mapping: thread -> (row, 4 consecutive k)
    const int mA  = t >> 1;
    const int kA4 = (t & 1) * 4;
    // B-load mapping: thread -> (k row, 4 consecutive n)
    const int kB  = t >> 5;
    const int nB4 = (t & 31) * 4;

    const int p = m0 + mA;
    const int h = p / FW_, w = p % FW_;

    const int tx = t & 15, ty = t >> 4;

    unsigned long long acc2[8][4];       // (acc[i][2j], acc[i][2j+1]) pairs
#pragma unroll
    for (int i = 0; i < 8; ++i)
#pragma unroll
        for (int j = 0; j < 4; ++j) acc2[i][j] = 0ull;

    auto loadA = [&](int kt) -> float4 {
        int k0  = kt * 8;
        int tap = k0 >> 9;              // /512 (BK=8 divides 512, tap uniform per tile)
        int ci  = (k0 & 511) + kA4;
        int hh  = h + (tap / 3) - 1;
        int ww  = w + (tap % 3) - 1;
        if (hh < 0 || hh >= FH_ || ww < 0 || ww >= FW_) return make_float4(0.f, 0.f, 0.f, 0.f);
        return *(const float4*)(fm + ((size_t)(hh * FW_ + ww) * 512 + ci));
    };
    auto loadB = [&](int kt) -> float4 {
        int k0 = kt * 8 + kB;
        return *(const float4*)(W1 + ((size_t)k0 * 512 + n0 + nB4));
    };

    float4 ra = loadA(0);
    float4 rb = loadB(0);

    const int NKT = KTOT / 8;  // 576
    int buf = 0;
    for (int kt = 0; kt < NKT; ++kt) {
        // stage regs -> smem[buf]
        As[buf][kA4 + 0][mA] = ra.x;
        As[buf][kA4 + 1][mA] = ra.y;
        As[buf][kA4 + 2][mA] = ra.z;
        As[buf][kA4 + 3][mA] = ra.w;
        *(float4*)&Bs[buf][kB][nB4] = rb;
        __syncthreads();

        if (kt + 1 < NKT) { ra = loadA(kt + 1); rb = loadB(kt + 1); }

#pragma unroll
        for (int k = 0; k < 8; ++k) {
            float4 a0 = *(float4*)&As[buf][k][ty * 8];
            float4 a1 = *(float4*)&As[buf][k][ty * 8 + 4];
            float4 b0 = *(float4*)&Bs[buf][k][tx * 8];
            float4 b1v = *(float4*)&Bs[buf][k][tx * 8 + 4];
            unsigned long long bb[4];
            bb[0] = ((unsigned long long*)&b0)[0];
            bb[1] = ((unsigned long long*)&b0)[1];
            bb[2] = ((unsigned long long*)&b1v)[0];
            bb[3] = ((unsigned long long*)&b1v)[1];
            float av[8] = {a0.x, a0.y, a0.z, a0.w, a1.x, a1.y, a1.z, a1.w};
#pragma unroll
            for (int i = 0; i < 8; ++i) {
                unsigned long long aa = bcast2(av[i]);
                fma2(acc2[i][0], aa, bb[0]);
                fma2(acc2[i][1], aa, bb[1]);
                fma2(acc2[i][2], aa, bb[2]);
                fma2(acc2[i][3], aa, bb[3]);
            }
        }
        buf ^= 1;
    }

    // epilogue: bias + relu -> g_y
    float bs[8];
#pragma unroll
    for (int j = 0; j < 8; ++j) bs[j] = b1[n0 + tx * 8 + j];

#pragma unroll
    for (int i = 0; i < 8; ++i) {
        int pos = m0 + ty * 8 + i;
        float o[8];
#pragma unroll
        for (int j = 0; j < 4; ++j) {
            float lo, hi;
            unpack2(acc2[i][j], lo, hi);
            o[2 * j]     = fmaxf(lo + bs[2 * j], 0.f);
            o[2 * j + 1] = fmaxf(hi + bs[2 * j + 1], 0.f);
        }
        float* dst = g_y + (size_t)pos * 512 + n0 + tx * 8;
        *(float4*)(dst)     = make_float4(o[0], o[1], o[2], o[3]);
        *(float4*)(dst + 4) = make_float4(o[4], o[5], o[6], o[7]);
    }
}

// ---------------- 1x1 head convs: [16000 x 512] * [512 x 45] + sigmoid on scores ----------------
__global__ __launch_bounds__(256)
void k_head(const float* __restrict__ Wc, const float* __restrict__ bc,
            const float* __restrict__ Wr, const float* __restrict__ br,
            float* __restrict__ out) {
    __shared__ float sy[16 * 512];
    const int t  = threadIdx.x;
    const int p0 = blockIdx.x * 16;

    const float4* src  = (const float4*)(g_y + (size_t)p0 * 512);
    float4*       dst4 = (float4*)sy;
    for (int i = t; i < 16 * 128; i += 256) dst4[i] = src[i];
    __syncthreads();

    for (int e = t; e < 16 * 45; e += 256) {
        int pos = e / 45, o = e % 45;
        const float* wp;
        int   stride;
        float bias;
        if (o < 9) { wp = Wc + o;       stride = 9;  bias = bc[o];     }
        else       { wp = Wr + (o - 9); stride = 36; bias = br[o - 9]; }

        const float4* y4 = (const float4*)(sy + pos * 512);
        float acc = 0.f;
#pragma unroll 4
        for (int k4 = 0; k4 < 128; ++k4) {
            float4 yv = y4[k4];
            int kb = k4 * 4;
            acc += yv.x * wp[(kb + 0) * stride];
            acc += yv.y * wp[(kb + 1) * stride];
            acc += yv.z * wp[(kb + 2) * stride];
            acc += yv.w * wp[(kb + 3) * stride];
        }
        acc += bias;
        int gp = p0 + pos;
        if (o < 9) {
            out[OFF_SCORES + gp * 9 + o] = 1.f / (1.f + expf(-acc));
        } else {
            out[OFF_REG + gp * 36 + (o - 9)] = acc;
        }
    }
}

// ---------------- decode anchors + build sort keys ----------------
__global__ void k_decode(const float* __restrict__ am, const float* __restrict__ out) {
    int i = blockIdx.x * 256 + threadIdx.x;
    if (i >= NANCH) return;
    float  s = out[OFF_SCORES + i];                         // flatten [FH,FW,9] == i
    float4 d = *(const float4*)(out + OFF_REG + (size_t)i * 4);  // [.,36] flat == i*4
    float4 A = *(const float4*)(am + (size_t)i * 4);

    float ah = A.z - A.x, aw = A.w - A.y;
    float acy = A.x + 0.5f * ah, acx = A.y + 0.5f * aw;
    float cy = acy + d.x * ah, cx = acx + d.y * aw;
    float hh = ah * expf(d.z), ww = aw * expf(d.w);
    g_props[i] = make_float4(cy - 0.5f * hh, cx - 0.5f * ww, cy + 0.5f * hh, cx + 0.5f * ww);

    // score desc, then index asc (matches lax.top_k stable order / jnp.argmax first-max)
    unsigned int ob = __float_as_uint(s) | 0x80000000u;     // scores are >= 0
    g_keys[i] = ((unsigned long long)ob << 32) | (unsigned long long)(0xFFFFFFFFu - (unsigned)i);
}

// ---------------- exact top-6000 threshold: MSD radix select over u64 keys ----------------
__global__ void k_hist(int b) {
    __shared__ unsigned int sh[256];
    int t = threadIdx.x;
    if (t < 256) sh[t] = 0u;
    __syncthreads();
    unsigned long long pref = g_prefix;
    int shift = (b + 1) * 8;
    for (int i = blockIdx.x * blockDim.x + t; i < NANCH; i += gridDim.x * blockDim.x) {
        unsigned long long k = g_keys[i];
        if (b == 7 || (k >> shift) == (pref >> shift))
            atomicAdd(&sh[(unsigned int)(k >> (b * 8)) & 255u], 1u);
    }
    __syncthreads();
    if (t < 256 && sh[t]) atomicAdd(&g_hist[t], sh[t]);
}

__global__ void k_scan(int b) {
    if (threadIdx.x != 0) return;
    unsigned int r = g_rank, cum = 0;
    int d = 255;
    for (; d >= 0; --d) {
        unsigned int c = g_hist[d];
        if (cum + c >= r) break;
        cum += c;
    }
    if (d < 0) d = 0;  // defensive; cannot happen
    g_prefix |= ((unsigned long long)(unsigned int)d) << (b * 8);
    g_rank = r - cum;
    for (int j = 0; j < 256; ++j) g_hist[j] = 0u;
}

// ---------------- compact top-6000, clip + min-size filter ----------------
__global__ void k_compact() {
    int i = blockIdx.x * 256 + threadIdx.x;
    if (i >= NANCH) return;
    unsigned long long k = g_keys[i];
    if (k >= g_prefix) {                          // g_prefix == exact 6000th-largest key
        unsigned int slot = atomicAdd(&g_count, 1u);
        float4 pr = g_props[i];
        float y1 = fmaxf(pr.x, 0.f), x1 = fmaxf(pr.y, 0.f);
        float y2 = fminf(pr.z, IMG_H), x2 = fminf(pr.w, IMG_W);
        float hh = y2 - y1, ww = x2 - x1;
        if (!(hh >= 16.f && ww >= 16.f)) k = 0ull;  // min-size mask == NEG score
        g_cand_keys[slot]  = k;
        g_cand_boxes[slot] = make_float4(y1, x1, y2, x2);
    }
}

// ---------------- greedy NMS: single block, register-resident candidates ----------------
__global__ __launch_bounds__(1024)
void k_nms(float* __restrict__ out) {
    __shared__ unsigned long long wmax[32];
    __shared__ unsigned long long smax;
    __shared__ float4 ssel;

    const int t = threadIdx.x, lane = t & 31, warp = t >> 5;
    unsigned long long lk[6];
    float4 lb[6];
#pragma unroll
    for (int e = 0; e < 6; ++e) {
        int idx = e * 1024 + t;
        if (idx < PRE_NMS_) { lk[e] = g_cand_keys[idx]; lb[e] = g_cand_boxes[idx]; }
        else                { lk[e] = 0ull; lb[e] = make_float4(0.f, 0.f, 0.f, 0.f); }
    }
    float* outp = out + OFF_PROPS;

    for (int it = 0; it < POST_NMS_; ++it) {
        unsigned long long m = lk[0];
#pragma unroll
        for (int e = 1; e < 6; ++e) m = (lk[e] > m) ? lk[e] : m;
#pragma unroll
        for (int o = 16; o > 0; o >>= 1) {
            unsigned long long v = __shfl_down_sync(0xffffffffu, m, o);
            if (v > m) m = v;
        }
        if (lane == 0) wmax[warp] = m;
        __syncthreads();
        if (warp == 0) {
            unsigned long long v = wmax[lane];
#pragma unroll
            for (int o = 16; o > 0; o >>= 1) {
                unsigned long long v2 = __shfl_down_sync(0xffffffffu, v, o);
                if (v2 > v) v = v2;
            }
            if (lane == 0) smax = v;
        }
        __syncthreads();
        unsigned long long gm = smax;

        if (gm == 0ull) {          // all suppressed/invalid -> zero rows (uniform branch)
            if (t == 0) *(float4*)(outp + it * 4) = make_float4(0.f, 0.f, 0.f, 0.f);
            __syncthreads();
            continue;
        }
#pragma unroll
        for (int e = 0; e < 6; ++e) {
            if (lk[e] == gm) {     // unique owner (keys are unique)
                ssel = lb[e];
                *(float4*)(outp + it * 4) = lb[e];
                lk[e] = 0ull;
            }
        }
        __syncthreads();
        float4 s = ssel;
        float sa = fmaxf(s.z - s.x, 0.f) * fmaxf(s.w - s.y, 0.f);
#pragma unroll
        for (int e = 0; e < 6; ++e) {
            if (lk[e] != 0ull) {
                float yy1 = fmaxf(s.x, lb[e].x);
                float xx1 = fmaxf(s.y, lb[e].y);
                float yy2 = fminf(s.z, lb[e].z);
                float xx2 = fminf(s.w, lb[e].w);
                float inter = fmaxf(yy2 - yy1, 0.f) * fmaxf(xx2 - xx1, 0.f);
                float a2 = fmaxf(lb[e].z - lb[e].x, 0.f) * fmaxf(lb[e].w - lb[e].y, 0.f);
                float iou = inter / (sa + a2 - inter + 1e-8f);
                if (iou > 0.7f) lk[e] = 0ull;
            }
        }
        __syncthreads();
    }
}

// ---------------- launch ----------------
extern "C" void kernel_launch(void* const* d_in, const int* in_sizes, int n_in,
                              void* d_out, int out_size) {
    const float* fm = (const float*)d_in[1];
    const float* am = (const float*)d_in[2];
    const float* W1 = (const float*)d_in[4];
    const float* b1 = (const float*)d_in[5];
    const float* Wc = (const float*)d_in[6];
    const float* bc = (const float*)d_in[7];
    const float* Wr = (const float*)d_in[8];
    const float* br = (const float*)d_in[9];
    float* out = (float*)d_out;

    k_reset<<<1, 256>>>();
    k_conv3<<<dim3(125, 4), 256>>>(fm, W1, b1);
    k_head<<<1000, 256>>>(Wc, bc, Wr, br, out);
    k_decode<<<(NANCH + 255) / 256, 256>>>(am, out);
    for (int b = 7; b >= 0; --b) {
        k_hist<<<148, 256>>>(b);
        k_scan<<<1, 1>>>(b);
    }
    k_compact<<<(NANCH + 255) / 256, 256>>>();
    k_nms<<<1, 1024>>>(out);
}

// round 8
// speedup vs baseline: 1.7793x; 1.7793x over previous
#include <cuda_runtime.h>
#include <cstdint>

// ---------------- problem constants ----------------
#define FH_   100
#define FW_   160
#define NPOS  16000          // FH*FW
#define CIN   512
#define KTOT  4608           // 9*512
#define NANCH 144000         // NPOS*9
#define PRE_NMS_  6000
#define POST_NMS_ 300
#define IMG_H 1600.0f
#define IMG_W 2560.0f

#define OFF_SCORES 0
#define OFF_REG    144000
#define OFF_PROPS  720000

// ---------------- scratch (device globals; no allocation allowed) ----------------
__device__ float              g_AT[(size_t)KTOT * NPOS];  // 295MB zero-padded im2col^T
__device__ float              g_y[NPOS * 512];            // conv1 output
__device__ float4             g_props[NANCH];
__device__ unsigned long long g_keys[NANCH];
__device__ unsigned long long g_cand_keys[PRE_NMS_];
__device__ float4             g_cand_boxes[PRE_NMS_];
__device__ unsigned int       g_hist[256];
__device__ unsigned long long g_prefix;
__device__ unsigned int       g_rank;
__device__ unsigned int       g_count;

// ---------------- helpers ----------------
__device__ __forceinline__ uint32_t s2u(const void* p) {
    uint32_t a;
    asm("{ .reg .u64 t; cvta.to.shared.u64 t, %1; cvt.u32.u64 %0, t; }" : "=r"(a) : "l"(p));
    return a;
}
__device__ __forceinline__ void cp16(uint32_t dst, const void* src) {
    asm volatile("cp.async.cg.shared.global [%0], [%1], 16;" :: "r"(dst), "l"(src));
}

// ---------------- reset ----------------
__global__ void k_reset() {
    int t = threadIdx.x;
    if (t < 256) g_hist[t] = 0u;
    if (t == 0) { g_prefix = 0ull; g_rank = PRE_NMS_; g_count = 0u; }
}

// ---------------- prep: build zero-padded im2col transpose AT[k][m] ----------------
// AT[tap*512+ci][m] = valid(m,tap) ? fm[m + dh*160 + dw][ci] : 0
// block: (32,8), grid: (500 m-tiles, 16 ci-tiles, 9 taps)
__global__ __launch_bounds__(256)
void k_prep(const float* __restrict__ fm) {
    __shared__ float ts[32][33];
    const int tx = threadIdx.x;      // 0..31
    const int ty = threadIdx.y;      // 0..7
    const int m0  = blockIdx.x * 32;
    const int ci0 = blockIdx.y * 32;
    const int tap = blockIdx.z;
    const int dh = tap / 3 - 1, dw = tap % 3 - 1;
    const int delta = dh * FW_ + dw;

    // load: ts[m_local][ci_local], coalesced along ci; apply validity (zero pad)
    for (int r = ty; r < 32; r += 8) {
        int m = m0 + r;
        int h = m / FW_, w = m % FW_;
        bool ok = ((unsigned)(h + dh) < FH_) && ((unsigned)(w + dw) < FW_);
        ts[r][tx] = ok ? fm[(size_t)(m + delta) * 512 + ci0 + tx] : 0.f;
    }
    __syncthreads();
    // write transposed: AT[tap*512+ci][m], coalesced along m
    for (int r = ty; r < 32; r += 8) {
        g_AT[(size_t)(tap * 512 + ci0 + r) * NPOS + m0 + tx] = ts[tx][r];
    }
}

// ---------------- 3x3 conv as GEMM: C[16000,512] = AT^T * W1 ----------------
// BM=128, BN=128, BK=16, 3-stage cp.async pipeline.
// Consumer inner loop is BIT-IDENTICAL to the R1 passing kernel
// (per-output k-ascending scalar FFMA chain).
#define BK   16
#define NKT  (KTOT / BK)     // 288

__global__ __launch_bounds__(256, 2)
void k_conv3(const float* __restrict__ W1, const float* __restrict__ b1) {
    __shared__ float As[3][BK][128];
    __shared__ float Bs[3][BK][128];

    const int t  = threadIdx.x;
    const int m0 = blockIdx.x * 128;
    const int n0 = blockIdx.y * 128;
    const int tx = t & 15, ty = t >> 4;

    float acc[8][8];
#pragma unroll
    for (int i = 0; i < 8; ++i)
#pragma unroll
        for (int j = 0; j < 8; ++j) acc[i][j] = 0.f;

    auto loads = [&](int kt, int stg) {
        int K0 = kt * BK;
#pragma unroll
        for (int s = 0; s < 2; ++s) {
            int c  = t + s * 256;          // chunk id 0..511
            int k  = c >> 5;               // 0..15
            int mc = (c & 31) * 4;         // 0..124
            cp16(s2u(&As[stg][k][mc]), g_AT + (size_t)(K0 + k) * NPOS + m0 + mc);
            cp16(s2u(&Bs[stg][k][mc]), W1 + (size_t)(K0 + k) * 512 + n0 + mc);
        }
        asm volatile("cp.async.commit_group;" ::: "memory");
    };

    loads(0, 0);
    loads(1, 1);

    for (int kt = 0; kt < NKT; ++kt) {
        if (kt == NKT - 1) asm volatile("cp.async.wait_group 0;" ::: "memory");
        else               asm volatile("cp.async.wait_group 1;" ::: "memory");
        __syncthreads();
        if (kt + 2 < NKT) loads(kt + 2, (kt + 2) % 3);

        const int stg = kt % 3;
#pragma unroll
        for (int k = 0; k < BK; ++k) {
            float4 a0  = *(float4*)&As[stg][k][ty * 8];
            float4 a1  = *(float4*)&As[stg][k][ty * 8 + 4];
            float4 b0  = *(float4*)&Bs[stg][k][tx * 8];
            float4 b1v = *(float4*)&Bs[stg][k][tx * 8 + 4];
            float av[8] = {a0.x, a0.y, a0.z, a0.w, a1.x, a1.y, a1.z, a1.w};
            float bv[8] = {b0.x, b0.y, b0.z, b0.w, b1v.x, b1v.y, b1v.z, b1v.w};
#pragma unroll
            for (int i = 0; i < 8; ++i)
#pragma unroll
                for (int j = 0; j < 8; ++j) acc[i][j] += av[i] * bv[j];
        }
        __syncthreads();
    }

    // epilogue: bias + relu -> g_y (identical to R1)
    float bs[8];
#pragma unroll
    for (int j = 0; j < 8; ++j) bs[j] = b1[n0 + tx * 8 + j];

#pragma unroll
    for (int i = 0; i < 8; ++i) {
        int pos = m0 + ty * 8 + i;
        float o[8];
#pragma unroll
        for (int j = 0; j < 8; ++j) o[j] = fmaxf(acc[i][j] + bs[j], 0.f);
        float* dst = g_y + (size_t)pos * 512 + n0 + tx * 8;
        *(float4*)(dst)     = make_float4(o[0], o[1], o[2], o[3]);
        *(float4*)(dst + 4) = make_float4(o[4], o[5], o[6], o[7]);
    }
}

// ---------------- 1x1 head convs + sigmoid ----------------
__global__ __launch_bounds__(256)
void k_head(const float* __restrict__ Wc, const float* __restrict__ bc,
            const float* __restrict__ Wr, const float* __restrict__ br,
            float* __restrict__ out) {
    __shared__ float sy[16 * 512];
    const int t  = threadIdx.x;
    const int p0 = blockIdx.x * 16;

    const float4* src  = (const float4*)(g_y + (size_t)p0 * 512);
    float4*       dst4 = (float4*)sy;
    for (int i = t; i < 16 * 128; i += 256) dst4[i] = src[i];
    __syncthreads();

    for (int e = t; e < 16 * 45; e += 256) {
        int pos = e / 45, o = e % 45;
        const float* wp;
        int   stride;
        float bias;
        if (o < 9) { wp = Wc + o;       stride = 9;  bias = bc[o];     }
        else       { wp = Wr + (o - 9); stride = 36; bias = br[o - 9]; }

        const float4* y4 = (const float4*)(sy + pos * 512);
        float acc = 0.f;
#pragma unroll 4
        for (int k4 = 0; k4 < 128; ++k4) {
            float4 yv = y4[k4];
            int kb = k4 * 4;
            acc += yv.x * wp[(kb + 0) * stride];
            acc += yv.y * wp[(kb + 1) * stride];
            acc += yv.z * wp[(kb + 2) * stride];
            acc += yv.w * wp[(kb + 3) * stride];
        }
        acc += bias;
        int gp = p0 + pos;
        if (o < 9) {
            out[OFF_SCORES + gp * 9 + o] = 1.f / (1.f + expf(-acc));
        } else {
            out[OFF_REG + gp * 36 + (o - 9)] = acc;
        }
    }
}

// ---------------- decode anchors + build sort keys ----------------
__global__ void k_decode(const float* __restrict__ am, const float* __restrict__ out) {
    int i = blockIdx.x * 256 + threadIdx.x;
    if (i >= NANCH) return;
    float  s = out[OFF_SCORES + i];
    float4 d = *(const float4*)(out + OFF_REG + (size_t)i * 4);
    float4 A = *(const float4*)(am + (size_t)i * 4);

    float ah = A.z - A.x, aw = A.w - A.y;
    float acy = A.x + 0.5f * ah, acx = A.y + 0.5f * aw;
    float cy = acy + d.x * ah, cx = acx + d.y * aw;
    float hh = ah * expf(d.z), ww = aw * expf(d.w);
    g_props[i] = make_float4(cy - 0.5f * hh, cx - 0.5f * ww, cy + 0.5f * hh, cx + 0.5f * ww);

    unsigned int ob = __float_as_uint(s) | 0x80000000u;
    g_keys[i] = ((unsigned long long)ob << 32) | (unsigned long long)(0xFFFFFFFFu - (unsigned)i);
}

// ---------------- exact top-6000: MSD radix select ----------------
__global__ void k_hist(int b) {
    __shared__ unsigned int sh[256];
    int t = threadIdx.x;
    if (t < 256) sh[t] = 0u;
    __syncthreads();
    unsigned long long pref = g_prefix;
    int shift = (b + 1) * 8;
    for (int i = blockIdx.x * blockDim.x + t; i < NANCH; i += gridDim.x * blockDim.x) {
        unsigned long long k = g_keys[i];
        if (b == 7 || (k >> shift) == (pref >> shift))
            atomicAdd(&sh[(unsigned int)(k >> (b * 8)) & 255u], 1u);
    }
    __syncthreads();
    if (t < 256 && sh[t]) atomicAdd(&g_hist[t], sh[t]);
}

__global__ void k_scan(int b) {
    if (threadIdx.x != 0) return;
    unsigned int r = g_rank, cum = 0;
    int d = 255;
    for (; d >= 0; --d) {
        unsigned int c = g_hist[d];
        if (cum + c >= r) break;
        cum += c;
    }
    if (d < 0) d = 0;
    g_prefix |= ((unsigned long long)(unsigned int)d) << (b * 8);
    g_rank = r - cum;
    for (int j = 0; j < 256; ++j) g_hist[j] = 0u;
}

// ---------------- compact top-6000, clip + min-size filter ----------------
__global__ void k_compact() {
    int i = blockIdx.x * 256 + threadIdx.x;
    if (i >= NANCH) return;
    unsigned long long k = g_keys[i];
    if (k >= g_prefix) {
        unsigned int slot = atomicAdd(&g_count, 1u);
        float4 pr = g_props[i];
        float y1 = fmaxf(pr.x, 0.f), x1 = fmaxf(pr.y, 0.f);
        float y2 = fminf(pr.z, IMG_H), x2 = fminf(pr.w, IMG_W);
        float hh = y2 - y1, ww = x2 - x1;
        if (!(hh >= 16.f && ww >= 16.f)) k = 0ull;
        g_cand_keys[slot]  = k;
        g_cand_boxes[slot] = make_float4(y1, x1, y2, x2);
    }
}

// ---------------- greedy NMS: single block, register-resident ----------------
__global__ __launch_bounds__(1024)
void k_nms(float* __restrict__ out) {
    __shared__ unsigned long long wmax[32];
    __shared__ unsigned long long smax;
    __shared__ float4 ssel;

    const int t = threadIdx.x, lane = t & 31, warp = t >> 5;
    unsigned long long lk[6];
    float4 lb[6];
#pragma unroll
    for (int e = 0; e < 6; ++e) {
        int idx = e * 1024 + t;
        if (idx < PRE_NMS_) { lk[e] = g_cand_keys[idx]; lb[e] = g_cand_boxes[idx]; }
        else                { lk[e] = 0ull; lb[e] = make_float4(0.f, 0.f, 0.f, 0.f); }
    }
    float* outp = out + OFF_PROPS;

    for (int it = 0; it < POST_NMS_; ++it) {
        unsigned long long m = lk[0];
#pragma unroll
        for (int e = 1; e < 6; ++e) m = (lk[e] > m) ? lk[e] : m;
#pragma unroll
        for (int o = 16; o > 0; o >>= 1) {
            unsigned long long v = __shfl_down_sync(0xffffffffu, m, o);
            if (v > m) m = v;
        }
        if (lane == 0) wmax[warp] = m;
        __syncthreads();
        if (warp == 0) {
            unsigned long long v = wmax[lane];
#pragma unroll
            for (int o = 16; o > 0; o >>= 1) {
                unsigned long long v2 = __shfl_down_sync(0xffffffffu, v, o);
                if (v2 > v) v = v2;
            }
            if (lane == 0) smax = v;
        }
        __syncthreads();
        unsigned long long gm = smax;

        if (gm == 0ull) {
            if (t == 0) *(float4*)(outp + it * 4) = make_float4(0.f, 0.f, 0.f, 0.f);
            __syncthreads();
            continue;
        }
#pragma unroll
        for (int e = 0; e < 6; ++e) {
            if (lk[e] == gm) {
                ssel = lb[e];
                *(float4*)(outp + it * 4) = lb[e];
                lk[e] = 0ull;
            }
        }
        __syncthreads();
        float4 s = ssel;
        float sa = fmaxf(s.z - s.x, 0.f) * fmaxf(s.w - s.y, 0.f);
#pragma unroll
        for (int e = 0; e < 6; ++e) {
            if (lk[e] != 0ull) {
                float yy1 = fmaxf(s.x, lb[e].x);
                float xx1 = fmaxf(s.y, lb[e].y);
                float yy2 = fminf(s.z, lb[e].z);
                float xx2 = fminf(s.w, lb[e].w);
                float inter = fmaxf(yy2 - yy1, 0.f) * fmaxf(xx2 - xx1, 0.f);
                float a2 = fmaxf(lb[e].z - lb[e].x, 0.f) * fmaxf(lb[e].w - lb[e].y, 0.f);
                float iou = inter / (sa + a2 - inter + 1e-8f);
                if (iou > 0.7f) lk[e] = 0ull;
            }
        }
        __syncthreads();
    }
}

// ---------------- launch ----------------
extern "C" void kernel_launch(void* const* d_in, const int* in_sizes, int n_in,
                              void* d_out, int out_size) {
    const float* fm = (const float*)d_in[1];
    const float* am = (const float*)d_in[2];
    const float* W1 = (const float*)d_in[4];
    const float* b1 = (const float*)d_in[5];
    const float* Wc = (const float*)d_in[6];
    const float* bc = (const float*)d_in[7];
    const float* Wr = (const float*)d_in[8];
    const float* br = (const float*)d_in[9];
    float* out = (float*)d_out;

    k_reset<<<1, 256>>>();
    k_prep<<<dim3(500, 16, 9), dim3(32, 8)>>>(fm);
    k_conv3<<<dim3(125, 4), 256>>>(W1, b1);
    k_head<<<1000, 256>>>(Wc, bc, Wr, br, out);
    k_decode<<<(NANCH + 255) / 256, 256>>>(am, out);
    for (int b = 7; b >= 0; --b) {
        k_hist<<<148, 256>>>(b);
        k_scan<<<1, 1>>>(b);
    }
    k_compact<<<(NANCH + 255) / 256, 256>>>();
    k_nms<<<1, 1024>>>(out);
}

// round 9
// speedup vs baseline: 1.7966x; 1.0097x over previous
#include <cuda_runtime.h>
#include <cstdint>

// ---------------- problem constants ----------------
#define FH_   100
#define FW_   160
#define NPOS  16000          // FH*FW
#define CIN   512
#define KTOT  4608           // 9*512
#define NANCH 144000         // NPOS*9
#define PRE_NMS_  6000
#define POST_NMS_ 300
#define IMG_H 1600.0f
#define IMG_W 2560.0f

#define OFF_SCORES 0
#define OFF_REG    144000
#define OFF_PROPS  720000

// ---------------- scratch (device globals; no allocation allowed) ----------------
__device__ float              g_AT[(size_t)KTOT * NPOS];  // 295MB zero-padded im2col^T
__device__ float              g_y[NPOS * 512];            // conv1 output
__device__ float              g_wT[45 * 512];             // head weights transposed [o][k]
__device__ float4             g_props[NANCH];
__device__ unsigned long long g_keys[NANCH];
__device__ unsigned long long g_cand_keys[PRE_NMS_];
__device__ float4             g_cand_boxes[PRE_NMS_];
__device__ unsigned int       g_hist[256];
__device__ unsigned long long g_prefix;
__device__ unsigned int       g_rank;
__device__ unsigned int       g_count;

// ---------------- helpers ----------------
__device__ __forceinline__ uint32_t s2u(const void* p) {
    uint32_t a;
    asm("{ .reg .u64 t; cvta.to.shared.u64 t, %1; cvt.u32.u64 %0, t; }" : "=r"(a) : "l"(p));
    return a;
}
__device__ __forceinline__ void cp16(uint32_t dst, const void* src) {
    asm volatile("cp.async.cg.shared.global [%0], [%1], 16;" :: "r"(dst), "l"(src));
}

// ---------------- reset ----------------
__global__ void k_reset() {
    int t = threadIdx.x;
    if (t < 256) g_hist[t] = 0u;
    if (t == 0) { g_prefix = 0ull; g_rank = PRE_NMS_; g_count = 0u; }
}

// ---------------- prep: transpose head weights into wT[45][512] ----------------
__global__ void k_prep_w(const float* __restrict__ Wc, const float* __restrict__ Wr) {
    for (int i = blockIdx.x * 256 + threadIdx.x; i < 45 * 512; i += gridDim.x * 256) {
        int o = i >> 9, k = i & 511;
        g_wT[o * 512 + k] = (o < 9) ? Wc[k * 9 + o] : Wr[k * 36 + (o - 9)];
    }
}

// ---------------- prep: build zero-padded im2col transpose AT[k][m] ----------------
__global__ __launch_bounds__(256)
void k_prep(const float* __restrict__ fm) {
    __shared__ float ts[32][33];
    const int tx = threadIdx.x;      // 0..31
    const int ty = threadIdx.y;      // 0..7
    const int m0  = blockIdx.x * 32;
    const int ci0 = blockIdx.y * 32;
    const int tap = blockIdx.z;
    const int dh = tap / 3 - 1, dw = tap % 3 - 1;
    const int delta = dh * FW_ + dw;

    for (int r = ty; r < 32; r += 8) {
        int m = m0 + r;
        int h = m / FW_, w = m % FW_;
        bool ok = ((unsigned)(h + dh) < FH_) && ((unsigned)(w + dw) < FW_);
        ts[r][tx] = ok ? fm[(size_t)(m + delta) * 512 + ci0 + tx] : 0.f;
    }
    __syncthreads();
    for (int r = ty; r < 32; r += 8) {
        g_AT[(size_t)(tap * 512 + ci0 + r) * NPOS + m0 + tx] = ts[tx][r];
    }
}

// ---------------- 3x3 conv as GEMM: C[16000,512] = AT^T * W1 ----------------
#define BK   16
#define NKT  (KTOT / BK)     // 288

__global__ __launch_bounds__(256, 2)
void k_conv3(const float* __restrict__ W1, const float* __restrict__ b1) {
    __shared__ float As[3][BK][128];
    __shared__ float Bs[3][BK][128];

    const int t  = threadIdx.x;
    const int m0 = blockIdx.x * 128;
    const int n0 = blockIdx.y * 128;
    const int tx = t & 15, ty = t >> 4;

    float acc[8][8];
#pragma unroll
    for (int i = 0; i < 8; ++i)
#pragma unroll
        for (int j = 0; j < 8; ++j) acc[i][j] = 0.f;

    auto loads = [&](int kt, int stg) {
        int K0 = kt * BK;
#pragma unroll
        for (int s = 0; s < 2; ++s) {
            int c  = t + s * 256;
            int k  = c >> 5;
            int mc = (c & 31) * 4;
            cp16(s2u(&As[stg][k][mc]), g_AT + (size_t)(K0 + k) * NPOS + m0 + mc);
            cp16(s2u(&Bs[stg][k][mc]), W1 + (size_t)(K0 + k) * 512 + n0 + mc);
        }
        asm volatile("cp.async.commit_group;" ::: "memory");
    };

    loads(0, 0);
    loads(1, 1);

    for (int kt = 0; kt < NKT; ++kt) {
        if (kt == NKT - 1) asm volatile("cp.async.wait_group 0;" ::: "memory");
        else               asm volatile("cp.async.wait_group 1;" ::: "memory");
        __syncthreads();
        if (kt + 2 < NKT) loads(kt + 2, (kt + 2) % 3);

        const int stg = kt % 3;
#pragma unroll
        for (int k = 0; k < BK; ++k) {
            float4 a0  = *(float4*)&As[stg][k][ty * 8];
            float4 a1  = *(float4*)&As[stg][k][ty * 8 + 4];
            float4 b0  = *(float4*)&Bs[stg][k][tx * 8];
            float4 b1v = *(float4*)&Bs[stg][k][tx * 8 + 4];
            float av[8] = {a0.x, a0.y, a0.z, a0.w, a1.x, a1.y, a1.z, a1.w};
            float bv[8] = {b0.x, b0.y, b0.z, b0.w, b1v.x, b1v.y, b1v.z, b1v.w};
#pragma unroll
            for (int i = 0; i < 8; ++i)
#pragma unroll
                for (int j = 0; j < 8; ++j) acc[i][j] += av[i] * bv[j];
        }
        __syncthreads();
    }

    float bs[8];
#pragma unroll
    for (int j = 0; j < 8; ++j) bs[j] = b1[n0 + tx * 8 + j];

#pragma unroll
    for (int i = 0; i < 8; ++i) {
        int pos = m0 + ty * 8 + i;
        float o[8];
#pragma unroll
        for (int j = 0; j < 8; ++j) o[j] = fmaxf(acc[i][j] + bs[j], 0.f);
        float* dst = g_y + (size_t)pos * 512 + n0 + tx * 8;
        *(float4*)(dst)     = make_float4(o[0], o[1], o[2], o[3]);
        *(float4*)(dst + 4) = make_float4(o[4], o[5], o[6], o[7]);
    }
}

// ---------------- 1x1 head convs + sigmoid (broadcast-friendly mapping) ----------------
// 16 threads of a warp share one output channel o -> weight loads are broadcast.
#define SYROW 516   // 512 + 4 pad floats: same-o threads' y reads -> 2-way not 16-way
__global__ __launch_bounds__(256)
void k_head(const float* __restrict__ bc, const float* __restrict__ br,
            float* __restrict__ out) {
    __shared__ float sy[16 * SYROW];
    const int t  = threadIdx.x;
    const int p0 = blockIdx.x * 16;

    // stage y tile: row-padded
    {
        const float4* src = (const float4*)(g_y + (size_t)p0 * 512);
        for (int i = t; i < 16 * 128; i += 256) {
            int pos = i >> 7, c = i & 127;
            ((float4*)(sy + pos * SYROW))[c] = src[i];
        }
    }
    __syncthreads();

    const int oBase = t >> 4;     // 0..15
    const int pos   = t & 15;
#pragma unroll
    for (int r = 0; r < 3; ++r) {
        int o = r * 16 + oBase;
        if (o < 45) {
            const float4* y4 = (const float4*)(sy + pos * SYROW);
            const float4* w4 = (const float4*)(g_wT + o * 512);
            float acc = 0.f;
#pragma unroll 4
            for (int k4 = 0; k4 < 128; ++k4) {
                float4 yv = y4[k4];
                float4 wv = w4[k4];
                acc += yv.x * wv.x;
                acc += yv.y * wv.y;
                acc += yv.z * wv.z;
                acc += yv.w * wv.w;
            }
            int gp = p0 + pos;
            if (o < 9) {
                acc += bc[o];
                out[OFF_SCORES + gp * 9 + o] = 1.f / (1.f + expf(-acc));
            } else {
                acc += br[o - 9];
                out[OFF_REG + gp * 36 + (o - 9)] = acc;
            }
        }
    }
}

// ---------------- decode anchors + build sort keys ----------------
__global__ void k_decode(const float* __restrict__ am, const float* __restrict__ out) {
    int i = blockIdx.x * 256 + threadIdx.x;
    if (i >= NANCH) return;
    float  s = out[OFF_SCORES + i];
    float4 d = *(const float4*)(out + OFF_REG + (size_t)i * 4);
    float4 A = *(const float4*)(am + (size_t)i * 4);

    float ah = A.z - A.x, aw = A.w - A.y;
    float acy = A.x + 0.5f * ah, acx = A.y + 0.5f * aw;
    float cy = acy + d.x * ah, cx = acx + d.y * aw;
    float hh = ah * expf(d.z), ww = aw * expf(d.w);
    g_props[i] = make_float4(cy - 0.5f * hh, cx - 0.5f * ww, cy + 0.5f * hh, cx + 0.5f * ww);

    unsigned int ob = __float_as_uint(s) | 0x80000000u;
    g_keys[i] = ((unsigned long long)ob << 32) | (unsigned long long)(0xFFFFFFFFu - (unsigned)i);
}

// ---------------- exact top-6000: MSD radix select ----------------
__global__ void k_hist(int b) {
    __shared__ unsigned int sh[256];
    int t = threadIdx.x;
    if (t < 256) sh[t] = 0u;
    __syncthreads();
    unsigned long long pref = g_prefix;
    int shift = (b + 1) * 8;
    for (int i = blockIdx.x * blockDim.x + t; i < NANCH; i += gridDim.x * blockDim.x) {
        unsigned long long k = g_keys[i];
        if (b == 7 || (k >> shift) == (pref >> shift))
            atomicAdd(&sh[(unsigned int)(k >> (b * 8)) & 255u], 1u);
    }
    __syncthreads();
    if (t < 256 && sh[t]) atomicAdd(&g_hist[t], sh[t]);
}

__global__ void k_scan(int b) {
    if (threadIdx.x != 0) return;
    unsigned int r = g_rank, cum = 0;
    int d = 255;
    for (; d >= 0; --d) {
        unsigned int c = g_hist[d];
        if (cum + c >= r) break;
        cum += c;
    }
    if (d < 0) d = 0;
    g_prefix |= ((unsigned long long)(unsigned int)d) << (b * 8);
    g_rank = r - cum;
    for (int j = 0; j < 256; ++j) g_hist[j] = 0u;
}

// ---------------- compact top-6000, clip + min-size filter ----------------
__global__ void k_compact() {
    int i = blockIdx.x * 256 + threadIdx.x;
    if (i >= NANCH) return;
    unsigned long long k = g_keys[i];
    if (k >= g_prefix) {
        unsigned int slot = atomicAdd(&g_count, 1u);
        float4 pr = g_props[i];
        float y1 = fmaxf(pr.x, 0.f), x1 = fmaxf(pr.y, 0.f);
        float y2 = fminf(pr.z, IMG_H), x2 = fminf(pr.w, IMG_W);
        float hh = y2 - y1, ww = x2 - x1;
        if (!(hh >= 16.f && ww >= 16.f)) k = 0ull;
        g_cand_keys[slot]  = k;
        g_cand_boxes[slot] = make_float4(y1, x1, y2, x2);
    }
}

// ---------------- greedy NMS: single block, register-resident ----------------
__global__ __launch_bounds__(1024)
void k_nms(float* __restrict__ out) {
    __shared__ unsigned long long wmax[32];
    __shared__ unsigned long long smax;
    __shared__ float4 ssel;

    const int t = threadIdx.x, lane = t & 31, warp = t >> 5;
    unsigned long long lk[6];
    float4 lb[6];
#pragma unroll
    for (int e = 0; e < 6; ++e) {
        int idx = e * 1024 + t;
        if (idx < PRE_NMS_) { lk[e] = g_cand_keys[idx]; lb[e] = g_cand_boxes[idx]; }
        else                { lk[e] = 0ull; lb[e] = make_float4(0.f, 0.f, 0.f, 0.f); }
    }
    float* outp = out + OFF_PROPS;

    for (int it = 0; it < POST_NMS_; ++it) {
        unsigned long long m = lk[0];
#pragma unroll
        for (int e = 1; e < 6; ++e) m = (lk[e] > m) ? lk[e] : m;
#pragma unroll
        for (int o = 16; o > 0; o >>= 1) {
            unsigned long long v = __shfl_down_sync(0xffffffffu, m, o);
            if (v > m) m = v;
        }
        if (lane == 0) wmax[warp] = m;
        __syncthreads();
        if (warp == 0) {
            unsigned long long v = wmax[lane];
#pragma unroll
            for (int o = 16; o > 0; o >>= 1) {
                unsigned long long v2 = __shfl_down_sync(0xffffffffu, v, o);
                if (v2 > v) v = v2;
            }
            if (lane == 0) smax = v;
        }
        __syncthreads();
        unsigned long long gm = smax;

        if (gm == 0ull) {
            if (t == 0) *(float4*)(outp + it * 4) = make_float4(0.f, 0.f, 0.f, 0.f);
            __syncthreads();
            continue;
        }
#pragma unroll
        for (int e = 0; e < 6; ++e) {
            if (lk[e] == gm) {
                ssel = lb[e];
                *(float4*)(outp + it * 4) = lb[e];
                lk[e] = 0ull;
            }
        }
        __syncthreads();
        float4 s = ssel;
        float sa = fmaxf(s.z - s.x, 0.f) * fmaxf(s.w - s.y, 0.f);
#pragma unroll
        for (int e = 0; e < 6; ++e) {
            if (lk[e] != 0ull) {
                float yy1 = fmaxf(s.x, lb[e].x);
                float xx1 = fmaxf(s.y, lb[e].y);
                float yy2 = fminf(s.z, lb[e].z);
                float xx2 = fminf(s.w, lb[e].w);
                float inter = fmaxf(yy2 - yy1, 0.f) * fmaxf(xx2 - xx1, 0.f);
                float a2 = fmaxf(lb[e].z - lb[e].x, 0.f) * fmaxf(lb[e].w - lb[e].y, 0.f);
                float iou = inter / (sa + a2 - inter + 1e-8f);
                if (iou > 0.7f) lk[e] = 0ull;
            }
        }
        __syncthreads();
    }
}

// ---------------- launch ----------------
extern "C" void kernel_launch(void* const* d_in, const int* in_sizes, int n_in,
                              void* d_out, int out_size) {
    const float* fm = (const float*)d_in[1];
    const float* am = (const float*)d_in[2];
    const float* W1 = (const float*)d_in[4];
    const float* b1 = (const float*)d_in[5];
    const float* Wc = (const float*)d_in[6];
    const float* bc = (const float*)d_in[7];
    const float* Wr = (const float*)d_in[8];
    const float* br = (const float*)d_in[9];
    float* out = (float*)d_out;

    k_reset<<<1, 256>>>();
    k_prep_w<<<12, 256>>>(Wc, Wr);
    k_prep<<<dim3(500, 16, 9), dim3(32, 8)>>>(fm);
    k_conv3<<<dim3(125, 4), 256>>>(W1, b1);
    k_head<<<1000, 256>>>(bc, br, out);
    k_decode<<<(NANCH + 255) / 256, 256>>>(am, out);
    for (int b = 7; b >= 0; --b) {
        k_hist<<<148, 256>>>(b);
        k_scan<<<1, 1>>>(b);
    }
    k_compact<<<(NANCH + 255) / 256, 256>>>();
    k_nms<<<1, 1024>>>(out);
}